// round 2
// baseline (speedup 1.0000x reference)
#include <cuda_runtime.h>
#include <math.h>
#include <cub/block/block_radix_sort.cuh>

#define DIMN 3
#define NPTS 30
#define KK   181
#define PP   24360          // 30*29*28
#define DE   190            // 9 + 181
#define RESTN 27

// K3 radix-sort config: 1024 threads * 24 items = 24576 >= PP, and PP = 1015*24 exactly
#define K3_THREADS 1024
#define K3_IPT     24
#define K3_TOTAL   (K3_THREADS * K3_IPT)
#define K3_VALID_T (PP / K3_IPT)          // 1015 fully-valid threads

// ------------------------- device scratch (static, allowed) -------------------------
__device__ float g_vec[(size_t)PP * DE];                 // (P, 190)
__device__ float g_wsT[190 * 192];                       // Ws_out transposed, padded
__device__ __align__(16) float g_sm2T[(size_t)KK * PP];  // (K, P) column-major sm2

// ------------------------- K0: transpose Ws_out -------------------------
__global__ void k0_transpose(const float* __restrict__ WsOut) {
    int j = blockIdx.x;          // 0..189
    int t = threadIdx.x;         // 0..191
    g_wsT[j * 192 + t] = (t < KK) ? WsOut[t * DE + j] : 0.0f;
}

// ------------------------- K1: per-permutation vec rows -------------------------
__global__ void k1_vec(const float* __restrict__ matrix,
                       const float* __restrict__ WsIn,
                       const float* __restrict__ WdIn) {
    __shared__ float mS[DIMN * NPTS];      // 90
    __shared__ float projS[DIMN][RESTN];   // 3x27
    __shared__ float gramS[9];

    const int p = blockIdx.x;
    const int t = threadIdx.x;             // 0..191

    // decode lexicographic permutation p -> (a,b,c)
    int a  = p / 812;                // 812 = 29*28
    int r  = p - a * 812;
    int bi = r / 28;
    int ci = r - bi * 28;
    int b  = bi + (bi >= a);
    int e0 = min(a, b), e1 = max(a, b);
    int c  = ci + (ci >= e0);
    c += (c >= e1);

    // sorted excluded triple for rest[]
    int s0 = min(a, min(b, c));
    int s2 = max(a, max(b, c));
    int s1 = a + b + c - s0 - s2;

    if (t < DIMN * NPTS) mS[t] = matrix[t];
    __syncthreads();

    if (t < DIMN * RESTN) {
        int i = t / RESTN, m = t - i * RESTN;
        int rm = m + (m >= s0); rm += (rm >= s1); rm += (rm >= s2);
        int ci_ = (i == 0) ? a : ((i == 1) ? b : c);
        projS[i][m] = mS[ci_] * mS[rm]
                    + mS[NPTS + ci_] * mS[NPTS + rm]
                    + mS[2 * NPTS + ci_] * mS[2 * NPTS + rm];
    } else if (t < DIMN * RESTN + 9) {
        int q = t - DIMN * RESTN;
        int i = q / 3, j = q - 3 * i;
        int ci_ = (i == 0) ? a : ((i == 1) ? b : c);
        int cj_ = (j == 0) ? a : ((j == 1) ? b : c);
        gramS[q] = mS[ci_] * mS[cj_]
                 + mS[NPTS + ci_] * mS[NPTS + cj_]
                 + mS[2 * NPTS + ci_] * mS[2 * NPTS + cj_];
    }
    __syncthreads();

    float* vrow = g_vec + (size_t)p * DE;
    if (t < 9) vrow[t] = gramS[t];

    if (t < KK) {
        const int k = t;
        const float w0 = WsIn[k * 3 + 0];
        const float w1 = WsIn[k * 3 + 1];
        const float w2 = WsIn[k * 3 + 2];

        float v[32];
#pragma unroll
        for (int m = 0; m < RESTN; ++m)
            v[m] = fmaf(projS[2][m], w2, fmaf(projS[1][m], w1, projS[0][m] * w0));
        const float INF = __int_as_float(0x7f800000);
#pragma unroll
        for (int m = RESTN; m < 32; ++m) v[m] = INF;

        // Batcher odd-even mergesort network for 32 elements (191 comparators,
        // all ascending), fully unrolled into registers.
#pragma unroll
        for (int pw = 1; pw < 32; pw <<= 1) {
#pragma unroll
            for (int kq = pw; kq >= 1; kq >>= 1) {
#pragma unroll
                for (int j = (kq % pw); j + kq < 32; j += 2 * kq) {
#pragma unroll
                    for (int i = 0; i < kq; ++i) {
                        int lo = i + j, hi = i + j + kq;
                        if (hi < 32 && (lo / (2 * pw)) == (hi / (2 * pw))) {
                            float x = v[lo], y = v[hi];
                            v[lo] = fminf(x, y);
                            v[hi] = fmaxf(x, y);
                        }
                    }
                }
            }
        }

        float e = 0.0f;
        const float* wd = WdIn + k * RESTN;
#pragma unroll
        for (int m = 0; m < RESTN; ++m) e = fmaf(wd[m], v[m], e);
        vrow[9 + k] = e;
    }
}

// ------------------------- K2: sm2T[k][p] = vec[p] . Ws_out[k] -------------------------
#define TP 64
#define JC 19
__global__ void k2_gemm() {
    __shared__ __align__(16) float vS[JC][TP];    // [j][p]
    __shared__ __align__(16) float wS[JC][192];   // [j][k]

    const int p0 = blockIdx.x * TP;
    const int t  = threadIdx.x;         // 256
    const int pt = t & 15;              // 16 p-threads
    const int kt = t >> 4;              // 16 k-threads

    float acc[4][12];
#pragma unroll
    for (int r0 = 0; r0 < 4; ++r0)
#pragma unroll
        for (int cc = 0; cc < 12; ++cc) acc[r0][cc] = 0.0f;

    for (int j0 = 0; j0 < DE; j0 += JC) {
        __syncthreads();
        for (int idx = t; idx < JC * TP; idx += 256) {
            int row = idx >> 6;              // /64
            int col = idx & 63;
            int p = p0 + col;
            vS[row][col] = (p < PP) ? g_vec[(size_t)p * DE + (j0 + row)] : 0.0f;
        }
        for (int idx = t; idx < JC * 192; idx += 256) {
            int row = idx / 192;
            int col = idx - row * 192;
            wS[row][col] = g_wsT[(j0 + row) * 192 + col];
        }
        __syncthreads();

#pragma unroll
        for (int jj = 0; jj < JC; ++jj) {
            float4 rv = *reinterpret_cast<const float4*>(&vS[jj][pt * 4]);
            float rr[4] = {rv.x, rv.y, rv.z, rv.w};
            const float4* wrow = reinterpret_cast<const float4*>(&wS[jj][0]);
            float4 wa = wrow[kt * 3 + 0];
            float4 wb = wrow[kt * 3 + 1];
            float4 wc = wrow[kt * 3 + 2];
            float w[12] = {wa.x, wa.y, wa.z, wa.w,
                           wb.x, wb.y, wb.z, wb.w,
                           wc.x, wc.y, wc.z, wc.w};
#pragma unroll
            for (int cc = 0; cc < 12; ++cc) {
#pragma unroll
                for (int r0 = 0; r0 < 4; ++r0)
                    acc[r0][cc] = fmaf(rr[r0], w[cc], acc[r0][cc]);
            }
        }
    }

    const bool full = (p0 + TP <= PP);
#pragma unroll
    for (int cc = 0; cc < 12; ++cc) {
        int k = kt * 12 + cc;
        if (k >= KK) continue;
        size_t base = (size_t)k * PP + p0 + pt * 4;
        if (full) {
            float4 val = make_float4(acc[0][cc], acc[1][cc], acc[2][cc], acc[3][cc]);
            *reinterpret_cast<float4*>(&g_sm2T[base]) = val;
        } else {
#pragma unroll
            for (int r0 = 0; r0 < 4; ++r0) {
                int p = p0 + pt * 4 + r0;
                if (p < PP) g_sm2T[(size_t)k * PP + p] = acc[r0][cc];
            }
        }
    }
}

// ------------------------- K3: per-k block radix sort + weighted reduce ----------------
using K3Sorter = cub::BlockRadixSort<float, K3_THREADS, K3_IPT, cub::NullType, 5>;

__global__ void __launch_bounds__(K3_THREADS, 1)
k3_sortdot(const float* __restrict__ WdOut, float* __restrict__ out) {
    extern __shared__ __align__(16) char smem_raw[];
    typename K3Sorter::TempStorage& tmp =
        *reinterpret_cast<typename K3Sorter::TempStorage*>(smem_raw);
    __shared__ float red[32];

    const int k = blockIdx.x;
    const int t = threadIdx.x;
    const float INF = __int_as_float(0x7f800000);

    float keys[K3_IPT];
    if (t < K3_VALID_T) {
        // blocked load: thread t owns elements [t*24, t*24+24), 16B-aligned
        const float4* src = reinterpret_cast<const float4*>(
            g_sm2T + (size_t)k * PP + (size_t)t * K3_IPT);
#pragma unroll
        for (int q = 0; q < K3_IPT / 4; ++q) {
            float4 v = src[q];
            keys[q * 4 + 0] = v.x;
            keys[q * 4 + 1] = v.y;
            keys[q * 4 + 2] = v.z;
            keys[q * 4 + 3] = v.w;
        }
    } else {
#pragma unroll
        for (int q = 0; q < K3_IPT; ++q) keys[q] = INF;
    }

    K3Sorter(tmp).Sort(keys);
    // after Sort: thread t holds ranks [t*24, t*24+24) ascending

    float acc = 0.0f;
    if (t < K3_VALID_T) {
        const float4* wrow = reinterpret_cast<const float4*>(
            WdOut + (size_t)k * PP + (size_t)t * K3_IPT);
#pragma unroll
        for (int q = 0; q < K3_IPT / 4; ++q) {
            float4 w = wrow[q];
            acc = fmaf(w.x, keys[q * 4 + 0], acc);
            acc = fmaf(w.y, keys[q * 4 + 1], acc);
            acc = fmaf(w.z, keys[q * 4 + 2], acc);
            acc = fmaf(w.w, keys[q * 4 + 3], acc);
        }
    }

#pragma unroll
    for (int o = 16; o > 0; o >>= 1)
        acc += __shfl_down_sync(0xffffffffu, acc, o);
    if ((t & 31) == 0) red[t >> 5] = acc;
    __syncthreads();
    if (t < 32) {
        float x = red[t];
#pragma unroll
        for (int o = 16; o > 0; o >>= 1)
            x += __shfl_down_sync(0xffffffffu, x, o);
        if (t == 0) out[k] = x;
    }
}

// ------------------------- launch -------------------------
extern "C" void kernel_launch(void* const* d_in, const int* in_sizes, int n_in,
                              void* d_out, int out_size) {
    const float* matrix = (const float*)d_in[0];
    const float* WsIn   = (const float*)d_in[1];
    const float* WdIn   = (const float*)d_in[2];
    const float* WsOut  = (const float*)d_in[3];
    const float* WdOut  = (const float*)d_in[4];
    float* out = (float*)d_out;

    const int k3_smem = (int)sizeof(typename K3Sorter::TempStorage);
    cudaFuncSetAttribute(k3_sortdot, cudaFuncAttributeMaxDynamicSharedMemorySize,
                         k3_smem);

    k0_transpose<<<DE, 192>>>(WsOut);
    k1_vec<<<PP, 192>>>(matrix, WsIn, WdIn);
    k2_gemm<<<(PP + TP - 1) / TP, 256>>>();
    k3_sortdot<<<KK, K3_THREADS, k3_smem>>>(WdOut, out);
}

// round 3
// speedup vs baseline: 2.2211x; 2.2211x over previous
#include <cuda_runtime.h>
#include <math.h>
#include <cub/block/block_radix_sort.cuh>

#define DIMN 3
#define NPTS 30
#define KK   181
#define PP   24360          // 30*29*28
#define DE   190            // 9 + 181
#define RESTN 27

// K3 radix-sort config: 1024 threads * 24 items = 24576 >= PP, PP = 1015*24 exactly
#define K3_THREADS 1024
#define K3_IPT     24
#define K3_VALID_T (PP / K3_IPT)          // 1015 fully-valid threads

// ------------------------- device scratch (static, allowed) -------------------------
__device__ float g_vec[(size_t)PP * DE];                 // (P, 190)
__device__ float g_wsT[190 * 192];                       // Ws_out transposed, padded
__device__ __align__(16) float g_sm2T[(size_t)KK * PP];  // (K, P) column-major sm2

// ------------------- compile-time Batcher odd-even merge network (27 wires) -------------
// Batcher-32 network (all comparators ascending), statically filtered to hi < 27:
// with +INF padding on wires 27..31, those comparators are exact no-ops.
struct CmpNet {
    int n;
    unsigned char lo[191];
    unsigned char hi[191];
};

constexpr CmpNet make_net() {
    CmpNet c{0, {}, {}};
    for (int p = 1; p < 32; p *= 2)
        for (int k = p; k >= 1; k /= 2)
            for (int j = k % p; j + k < 32; j += 2 * k)
                for (int i = 0; i < k && i + j + k < 32; ++i)
                    if ((i + j) / (2 * p) == (i + j + k) / (2 * p))
                        if (i + j + k < RESTN) {
                            c.lo[c.n] = (unsigned char)(i + j);
                            c.hi[c.n] = (unsigned char)(i + j + k);
                            ++c.n;
                        }
    return c;
}

constexpr CmpNet NET = make_net();

template <int Q>
__device__ __forceinline__ void net_steps(float* v) {
    constexpr int lo = NET.lo[Q];   // forced compile-time index
    constexpr int hi = NET.hi[Q];
    float x = v[lo], y = v[hi];
    v[lo] = fminf(x, y);
    v[hi] = fmaxf(x, y);
    if constexpr (Q + 1 < NET.n) net_steps<Q + 1>(v);
}

// ------------------------- K0: transpose Ws_out -------------------------
__global__ void k0_transpose(const float* __restrict__ WsOut) {
    int j = blockIdx.x;          // 0..189
    int t = threadIdx.x;         // 0..191
    g_wsT[j * 192 + t] = (t < KK) ? WsOut[t * DE + j] : 0.0f;
}

// ------------------------- K1: per-permutation vec rows -------------------------
__global__ void k1_vec(const float* __restrict__ matrix,
                       const float* __restrict__ WsIn,
                       const float* __restrict__ WdIn) {
    __shared__ float mS[DIMN * NPTS];      // 90
    __shared__ float projS[DIMN][RESTN];   // 3x27
    __shared__ float gramS[9];

    const int p = blockIdx.x;
    const int t = threadIdx.x;             // 0..191

    // decode lexicographic permutation p -> (a,b,c)
    int a  = p / 812;                // 812 = 29*28
    int r  = p - a * 812;
    int bi = r / 28;
    int ci = r - bi * 28;
    int b  = bi + (bi >= a);
    int e0 = min(a, b), e1 = max(a, b);
    int c  = ci + (ci >= e0);
    c += (c >= e1);

    // sorted excluded triple for rest[]
    int s0 = min(a, min(b, c));
    int s2 = max(a, max(b, c));
    int s1 = a + b + c - s0 - s2;

    if (t < DIMN * NPTS) mS[t] = matrix[t];
    __syncthreads();

    if (t < DIMN * RESTN) {
        int i = t / RESTN, m = t - i * RESTN;
        int rm = m + (m >= s0); rm += (rm >= s1); rm += (rm >= s2);
        int ci_ = (i == 0) ? a : ((i == 1) ? b : c);
        projS[i][m] = mS[ci_] * mS[rm]
                    + mS[NPTS + ci_] * mS[NPTS + rm]
                    + mS[2 * NPTS + ci_] * mS[2 * NPTS + rm];
    } else if (t < DIMN * RESTN + 9) {
        int q = t - DIMN * RESTN;
        int i = q / 3, j = q - 3 * i;
        int ci_ = (i == 0) ? a : ((i == 1) ? b : c);
        int cj_ = (j == 0) ? a : ((j == 1) ? b : c);
        gramS[q] = mS[ci_] * mS[cj_]
                 + mS[NPTS + ci_] * mS[NPTS + cj_]
                 + mS[2 * NPTS + ci_] * mS[2 * NPTS + cj_];
    }
    __syncthreads();

    float* vrow = g_vec + (size_t)p * DE;
    if (t < 9) vrow[t] = gramS[t];

    if (t < KK) {
        const int k = t;
        const float w0 = WsIn[k * 3 + 0];
        const float w1 = WsIn[k * 3 + 1];
        const float w2 = WsIn[k * 3 + 2];

        float v[RESTN];
#pragma unroll
        for (int m = 0; m < RESTN; ++m)
            v[m] = fmaf(projS[2][m], w2, fmaf(projS[1][m], w1, projS[0][m] * w0));

        // fully template-unrolled filtered Batcher network, ~155 comparators,
        // constant indices -> pure register file + FMNMX
        net_steps<0>(v);

        float e = 0.0f;
        const float* wd = WdIn + k * RESTN;
#pragma unroll
        for (int m = 0; m < RESTN; ++m) e = fmaf(wd[m], v[m], e);
        vrow[9 + k] = e;
    }
}

// ------------------------- K2: sm2T[k][p] = vec[p] . Ws_out[k] -------------------------
#define TP 64
#define JC 19
__global__ void k2_gemm() {
    __shared__ __align__(16) float vS[JC][TP];    // [j][p]
    __shared__ __align__(16) float wS[JC][192];   // [j][k]

    const int p0 = blockIdx.x * TP;
    const int t  = threadIdx.x;         // 256
    const int pt = t & 15;              // 16 p-threads
    const int kt = t >> 4;              // 16 k-threads

    float acc[4][12];
#pragma unroll
    for (int r0 = 0; r0 < 4; ++r0)
#pragma unroll
        for (int cc = 0; cc < 12; ++cc) acc[r0][cc] = 0.0f;

    for (int j0 = 0; j0 < DE; j0 += JC) {
        __syncthreads();
        for (int idx = t; idx < JC * TP; idx += 256) {
            int row = idx >> 6;              // /64
            int col = idx & 63;
            int p = p0 + col;
            vS[row][col] = (p < PP) ? g_vec[(size_t)p * DE + (j0 + row)] : 0.0f;
        }
        for (int idx = t; idx < JC * 192; idx += 256) {
            int row = idx / 192;
            int col = idx - row * 192;
            wS[row][col] = g_wsT[(j0 + row) * 192 + col];
        }
        __syncthreads();

#pragma unroll
        for (int jj = 0; jj < JC; ++jj) {
            float4 rv = *reinterpret_cast<const float4*>(&vS[jj][pt * 4]);
            float rr[4] = {rv.x, rv.y, rv.z, rv.w};
            const float4* wrow = reinterpret_cast<const float4*>(&wS[jj][0]);
            float4 wa = wrow[kt * 3 + 0];
            float4 wb = wrow[kt * 3 + 1];
            float4 wc = wrow[kt * 3 + 2];
            float w[12] = {wa.x, wa.y, wa.z, wa.w,
                           wb.x, wb.y, wb.z, wb.w,
                           wc.x, wc.y, wc.z, wc.w};
#pragma unroll
            for (int cc = 0; cc < 12; ++cc) {
#pragma unroll
                for (int r0 = 0; r0 < 4; ++r0)
                    acc[r0][cc] = fmaf(rr[r0], w[cc], acc[r0][cc]);
            }
        }
    }

    const bool full = (p0 + TP <= PP);
#pragma unroll
    for (int cc = 0; cc < 12; ++cc) {
        int k = kt * 12 + cc;
        if (k >= KK) continue;
        size_t base = (size_t)k * PP + p0 + pt * 4;
        if (full) {
            float4 val = make_float4(acc[0][cc], acc[1][cc], acc[2][cc], acc[3][cc]);
            *reinterpret_cast<float4*>(&g_sm2T[base]) = val;
        } else {
#pragma unroll
            for (int r0 = 0; r0 < 4; ++r0) {
                int p = p0 + pt * 4 + r0;
                if (p < PP) g_sm2T[(size_t)k * PP + p] = acc[r0][cc];
            }
        }
    }
}

// ------------------------- K3: per-k block radix sort + weighted reduce ----------------
using K3Sorter = cub::BlockRadixSort<float, K3_THREADS, K3_IPT, cub::NullType, 5>;

__global__ void __launch_bounds__(K3_THREADS, 1)
k3_sortdot(const float* __restrict__ WdOut, float* __restrict__ out) {
    extern __shared__ __align__(16) char smem_raw[];
    typename K3Sorter::TempStorage& tmp =
        *reinterpret_cast<typename K3Sorter::TempStorage*>(smem_raw);
    __shared__ float red[32];

    const int k = blockIdx.x;
    const int t = threadIdx.x;
    const float INF = __int_as_float(0x7f800000);

    float keys[K3_IPT];
    if (t < K3_VALID_T) {
        const float4* src = reinterpret_cast<const float4*>(
            g_sm2T + (size_t)k * PP + (size_t)t * K3_IPT);
#pragma unroll
        for (int q = 0; q < K3_IPT / 4; ++q) {
            float4 v = src[q];
            keys[q * 4 + 0] = v.x;
            keys[q * 4 + 1] = v.y;
            keys[q * 4 + 2] = v.z;
            keys[q * 4 + 3] = v.w;
        }
    } else {
#pragma unroll
        for (int q = 0; q < K3_IPT; ++q) keys[q] = INF;
    }

    K3Sorter(tmp).Sort(keys);
    // after Sort: thread t holds ranks [t*24, t*24+24) ascending

    float acc = 0.0f;
    if (t < K3_VALID_T) {
        const float4* wrow = reinterpret_cast<const float4*>(
            WdOut + (size_t)k * PP + (size_t)t * K3_IPT);
#pragma unroll
        for (int q = 0; q < K3_IPT / 4; ++q) {
            float4 w = wrow[q];
            acc = fmaf(w.x, keys[q * 4 + 0], acc);
            acc = fmaf(w.y, keys[q * 4 + 1], acc);
            acc = fmaf(w.z, keys[q * 4 + 2], acc);
            acc = fmaf(w.w, keys[q * 4 + 3], acc);
        }
    }

#pragma unroll
    for (int o = 16; o > 0; o >>= 1)
        acc += __shfl_down_sync(0xffffffffu, acc, o);
    if ((t & 31) == 0) red[t >> 5] = acc;
    __syncthreads();
    if (t < 32) {
        float x = red[t];
#pragma unroll
        for (int o = 16; o > 0; o >>= 1)
            x += __shfl_down_sync(0xffffffffu, x, o);
        if (t == 0) out[k] = x;
    }
}

// ------------------------- launch -------------------------
extern "C" void kernel_launch(void* const* d_in, const int* in_sizes, int n_in,
                              void* d_out, int out_size) {
    const float* matrix = (const float*)d_in[0];
    const float* WsIn   = (const float*)d_in[1];
    const float* WdIn   = (const float*)d_in[2];
    const float* WsOut  = (const float*)d_in[3];
    const float* WdOut  = (const float*)d_in[4];
    float* out = (float*)d_out;

    const int k3_smem = (int)sizeof(typename K3Sorter::TempStorage);
    cudaFuncSetAttribute(k3_sortdot, cudaFuncAttributeMaxDynamicSharedMemorySize,
                         k3_smem);

    k0_transpose<<<DE, 192>>>(WsOut);
    k1_vec<<<PP, 192>>>(matrix, WsIn, WdIn);
    k2_gemm<<<(PP + TP - 1) / TP, 256>>>();
    k3_sortdot<<<KK, K3_THREADS, k3_smem>>>(WdOut, out);
}

// round 4
// speedup vs baseline: 3.2961x; 1.4840x over previous
#include <cuda_runtime.h>
#include <math.h>
#include <cub/block/block_radix_sort.cuh>

#define DIMN 3
#define NPTS 30
#define KK   181
#define PP   24360          // 30*29*28
#define DE   190            // 9 + 181
#define RESTN 27

// K3 radix-sort config: 1024 threads * 24 items = 24576 >= PP, PP = 1015*24 exactly
#define K3_THREADS 1024
#define K3_IPT     24
#define K3_VALID_T (PP / K3_IPT)          // 1015 fully-valid threads

// ------------------------- device scratch (static, allowed) -------------------------
__device__ __align__(16) float g_vecT[(size_t)DE * PP]; // (190, P) TRANSPOSED vec
__device__ float g_wsT[190 * 192];                      // Ws_out transposed, padded
__device__ float g_wdT[RESTN * KK];                     // WdIn transposed (27, 181)
__device__ __align__(16) float g_sm2T[(size_t)KK * PP]; // (K, P) column-major sm2

// ------------------------- K0: transpose Ws_out -------------------------
__global__ void k0_transpose(const float* __restrict__ WsOut) {
    int j = blockIdx.x;          // 0..189
    int t = threadIdx.x;         // 0..191
    g_wsT[j * 192 + t] = (t < KK) ? WsOut[t * DE + j] : 0.0f;
}

// ------------------------- K0b: transpose Wd_in -------------------------
__global__ void k0b_transpose(const float* __restrict__ WdIn) {
    int m = blockIdx.x;          // 0..26
    int t = threadIdx.x;         // 0..191
    if (t < KK) g_wdT[m * KK + t] = WdIn[t * RESTN + m];
}

// ------------------------- K1: per-permutation vec rows (transposed store) ------------
__global__ void k1_vec(const float* __restrict__ matrix,
                       const float* __restrict__ WsIn) {
    __shared__ float mS[DIMN * NPTS];      // 90
    __shared__ float projS[DIMN][RESTN];   // 3x27
    __shared__ float gramS[9];

    const int p = blockIdx.x;
    const int t = threadIdx.x;             // 0..191

    // decode lexicographic permutation p -> (a,b,c)
    int a  = p / 812;                // 812 = 29*28
    int r  = p - a * 812;
    int bi = r / 28;
    int ci = r - bi * 28;
    int b  = bi + (bi >= a);
    int e0 = min(a, b), e1 = max(a, b);
    int c  = ci + (ci >= e0);
    c += (c >= e1);

    // sorted excluded triple for rest[]
    int s0 = min(a, min(b, c));
    int s2 = max(a, max(b, c));
    int s1 = a + b + c - s0 - s2;

    if (t < DIMN * NPTS) mS[t] = matrix[t];
    __syncthreads();

    if (t < DIMN * RESTN) {
        int i = t / RESTN, m = t - i * RESTN;
        int rm = m + (m >= s0); rm += (rm >= s1); rm += (rm >= s2);
        int ci_ = (i == 0) ? a : ((i == 1) ? b : c);
        projS[i][m] = mS[ci_] * mS[rm]
                    + mS[NPTS + ci_] * mS[NPTS + rm]
                    + mS[2 * NPTS + ci_] * mS[2 * NPTS + rm];
    } else if (t < DIMN * RESTN + 9) {
        int q = t - DIMN * RESTN;
        int i = q / 3, j = q - 3 * i;
        int ci_ = (i == 0) ? a : ((i == 1) ? b : c);
        int cj_ = (j == 0) ? a : ((j == 1) ? b : c);
        gramS[q] = mS[ci_] * mS[cj_]
                 + mS[NPTS + ci_] * mS[NPTS + cj_]
                 + mS[2 * NPTS + ci_] * mS[2 * NPTS + cj_];
    }
    __syncthreads();

    if (t < 9) g_vecT[(size_t)t * PP + p] = gramS[t];

    if (t < KK) {
        const int k = t;
        const float w0 = WsIn[k * 3 + 0];
        const float w1 = WsIn[k * 3 + 1];
        const float w2 = WsIn[k * 3 + 2];

        float v[32];
#pragma unroll
        for (int m = 0; m < RESTN; ++m)
            v[m] = fmaf(projS[2][m], w2, fmaf(projS[1][m], w1, projS[0][m] * w0));
        const float INF = __int_as_float(0x7f800000);
#pragma unroll
        for (int m = RESTN; m < 32; ++m) v[m] = INF;

        // fully-unrolled 32-element bitonic sort (ascending), stays in registers
        // (round-1 proven formulation)
#pragma unroll
        for (int size = 2; size <= 32; size <<= 1) {
#pragma unroll
            for (int stride = size >> 1; stride > 0; stride >>= 1) {
#pragma unroll
                for (int i = 0; i < 32; ++i) {
                    int j = i ^ stride;
                    if (j > i) {
                        bool up = ((i & size) == 0);
                        float x = v[i], y = v[j];
                        float lo = fminf(x, y), hi = fmaxf(x, y);
                        v[i] = up ? lo : hi;
                        v[j] = up ? hi : lo;
                    }
                }
            }
        }

        float e = 0.0f;
#pragma unroll
        for (int m = 0; m < RESTN; ++m)
            e = fmaf(g_wdT[m * KK + k], v[m], e);   // coalesced, L1-resident
        g_vecT[(size_t)(9 + k) * PP + p] = e;
    }
}

// ------------------------- K2: sm2T[k][p] = vec[p] . Ws_out[k] -------------------------
#define TP 64
#define JC 19
__global__ void k2_gemm() {
    __shared__ __align__(16) float vS[JC][TP];    // [j][p]
    __shared__ __align__(16) float wS[JC][192];   // [j][k]

    const int p0 = blockIdx.x * TP;
    const int t  = threadIdx.x;         // 256
    const int pt = t & 15;              // 16 p-threads
    const int kt = t >> 4;              // 16 k-threads

    float acc[4][12];
#pragma unroll
    for (int r0 = 0; r0 < 4; ++r0)
#pragma unroll
        for (int cc = 0; cc < 12; ++cc) acc[r0][cc] = 0.0f;

    for (int j0 = 0; j0 < DE; j0 += JC) {
        __syncthreads();
        for (int idx = t; idx < JC * TP; idx += 256) {
            int row = idx >> 6;              // j within tile
            int col = idx & 63;              // p within tile
            int p = p0 + col;
            // coalesced: consecutive threads -> consecutive p
            vS[row][col] = (p < PP) ? g_vecT[(size_t)(j0 + row) * PP + p] : 0.0f;
        }
        for (int idx = t; idx < JC * 192; idx += 256) {
            int row = idx / 192;
            int col = idx - row * 192;
            wS[row][col] = g_wsT[(j0 + row) * 192 + col];
        }
        __syncthreads();

#pragma unroll
        for (int jj = 0; jj < JC; ++jj) {
            float4 rv = *reinterpret_cast<const float4*>(&vS[jj][pt * 4]);
            float rr[4] = {rv.x, rv.y, rv.z, rv.w};
            const float4* wrow = reinterpret_cast<const float4*>(&wS[jj][0]);
            float4 wa = wrow[kt * 3 + 0];
            float4 wb = wrow[kt * 3 + 1];
            float4 wc = wrow[kt * 3 + 2];
            float w[12] = {wa.x, wa.y, wa.z, wa.w,
                           wb.x, wb.y, wb.z, wb.w,
                           wc.x, wc.y, wc.z, wc.w};
#pragma unroll
            for (int cc = 0; cc < 12; ++cc) {
#pragma unroll
                for (int r0 = 0; r0 < 4; ++r0)
                    acc[r0][cc] = fmaf(rr[r0], w[cc], acc[r0][cc]);
            }
        }
    }

    const bool full = (p0 + TP <= PP);
#pragma unroll
    for (int cc = 0; cc < 12; ++cc) {
        int k = kt * 12 + cc;
        if (k >= KK) continue;
        size_t base = (size_t)k * PP + p0 + pt * 4;
        if (full) {
            float4 val = make_float4(acc[0][cc], acc[1][cc], acc[2][cc], acc[3][cc]);
            *reinterpret_cast<float4*>(&g_sm2T[base]) = val;
        } else {
#pragma unroll
            for (int r0 = 0; r0 < 4; ++r0) {
                int p = p0 + pt * 4 + r0;
                if (p < PP) g_sm2T[(size_t)k * PP + p] = acc[r0][cc];
            }
        }
    }
}

// ------------------------- K3: per-k block radix sort + weighted reduce ----------------
using K3Sorter = cub::BlockRadixSort<float, K3_THREADS, K3_IPT, cub::NullType, 5>;

__global__ void __launch_bounds__(K3_THREADS, 1)
k3_sortdot(const float* __restrict__ WdOut, float* __restrict__ out) {
    extern __shared__ __align__(16) char smem_raw[];
    typename K3Sorter::TempStorage& tmp =
        *reinterpret_cast<typename K3Sorter::TempStorage*>(smem_raw);
    __shared__ float red[32];

    const int k = blockIdx.x;
    const int t = threadIdx.x;
    const float INF = __int_as_float(0x7f800000);

    float keys[K3_IPT];
    if (t < K3_VALID_T) {
        const float4* src = reinterpret_cast<const float4*>(
            g_sm2T + (size_t)k * PP + (size_t)t * K3_IPT);
#pragma unroll
        for (int q = 0; q < K3_IPT / 4; ++q) {
            float4 v = src[q];
            keys[q * 4 + 0] = v.x;
            keys[q * 4 + 1] = v.y;
            keys[q * 4 + 2] = v.z;
            keys[q * 4 + 3] = v.w;
        }
    } else {
#pragma unroll
        for (int q = 0; q < K3_IPT; ++q) keys[q] = INF;
    }

    K3Sorter(tmp).Sort(keys);
    // after Sort: thread t holds ranks [t*24, t*24+24) ascending

    float acc = 0.0f;
    if (t < K3_VALID_T) {
        const float4* wrow = reinterpret_cast<const float4*>(
            WdOut + (size_t)k * PP + (size_t)t * K3_IPT);
#pragma unroll
        for (int q = 0; q < K3_IPT / 4; ++q) {
            float4 w = wrow[q];
            acc = fmaf(w.x, keys[q * 4 + 0], acc);
            acc = fmaf(w.y, keys[q * 4 + 1], acc);
            acc = fmaf(w.z, keys[q * 4 + 2], acc);
            acc = fmaf(w.w, keys[q * 4 + 3], acc);
        }
    }

#pragma unroll
    for (int o = 16; o > 0; o >>= 1)
        acc += __shfl_down_sync(0xffffffffu, acc, o);
    if ((t & 31) == 0) red[t >> 5] = acc;
    __syncthreads();
    if (t < 32) {
        float x = red[t];
#pragma unroll
        for (int o = 16; o > 0; o >>= 1)
            x += __shfl_down_sync(0xffffffffu, x, o);
        if (t == 0) out[k] = x;
    }
}

// ------------------------- launch -------------------------
extern "C" void kernel_launch(void* const* d_in, const int* in_sizes, int n_in,
                              void* d_out, int out_size) {
    const float* matrix = (const float*)d_in[0];
    const float* WsIn   = (const float*)d_in[1];
    const float* WdIn   = (const float*)d_in[2];
    const float* WsOut  = (const float*)d_in[3];
    const float* WdOut  = (const float*)d_in[4];
    float* out = (float*)d_out;

    const int k3_smem = (int)sizeof(typename K3Sorter::TempStorage);
    cudaFuncSetAttribute(k3_sortdot, cudaFuncAttributeMaxDynamicSharedMemorySize,
                         k3_smem);

    k0_transpose<<<DE, 192>>>(WsOut);
    k0b_transpose<<<RESTN, 192>>>(WdIn);
    k1_vec<<<PP, 192>>>(matrix, WsIn);
    k2_gemm<<<(PP + TP - 1) / TP, 256>>>();
    k3_sortdot<<<KK, K3_THREADS, k3_smem>>>(WdOut, out);
}

// round 5
// speedup vs baseline: 3.9672x; 1.2036x over previous
#include <cuda_runtime.h>
#include <math.h>
#include <cub/block/block_radix_sort.cuh>

#define DIMN 3
#define NPTS 30
#define KK   181
#define PP   24360          // 30*29*28
#define DE   190            // 9 + 181
#define RESTN 27

// K3 split-sort config: two halves of 12180, padded to 12288 = 512*24
#define HALF_N   12180
#define HALF_PAD 12288
#define K3A_THREADS 512
#define K3A_IPT     24

// ------------------------- device scratch (static, allowed) -------------------------
__device__ __align__(16) float g_vecT[(size_t)DE * PP]; // (190, P) TRANSPOSED vec
__device__ float g_wsT[190 * 192];                      // Ws_out transposed, padded
__device__ float g_wdT[RESTN * KK];                     // WdIn transposed (27, 181)
__device__ __align__(16) float g_sm2T[(size_t)KK * PP]; // (K, P) column-major sm2
__device__ __align__(16) float g_srt[(size_t)KK * 2 * HALF_PAD]; // sorted half-runs

// ------------------------- K0: transpose Ws_out -------------------------
__global__ void k0_transpose(const float* __restrict__ WsOut) {
    int j = blockIdx.x;          // 0..189
    int t = threadIdx.x;         // 0..191
    g_wsT[j * 192 + t] = (t < KK) ? WsOut[t * DE + j] : 0.0f;
}

// ------------------------- K0b: transpose Wd_in -------------------------
__global__ void k0b_transpose(const float* __restrict__ WdIn) {
    int m = blockIdx.x;          // 0..26
    int t = threadIdx.x;         // 0..191
    if (t < KK) g_wdT[m * KK + t] = WdIn[t * RESTN + m];
}

// ------------------------- K1: per-permutation vec rows (transposed store) ------------
__global__ void k1_vec(const float* __restrict__ matrix,
                       const float* __restrict__ WsIn) {
    __shared__ float mS[DIMN * NPTS];      // 90
    __shared__ float projS[DIMN][RESTN];   // 3x27
    __shared__ float gramS[9];

    const int p = blockIdx.x;
    const int t = threadIdx.x;             // 0..191

    // decode lexicographic permutation p -> (a,b,c)
    int a  = p / 812;                // 812 = 29*28
    int r  = p - a * 812;
    int bi = r / 28;
    int ci = r - bi * 28;
    int b  = bi + (bi >= a);
    int e0 = min(a, b), e1 = max(a, b);
    int c  = ci + (ci >= e0);
    c += (c >= e1);

    // sorted excluded triple for rest[]
    int s0 = min(a, min(b, c));
    int s2 = max(a, max(b, c));
    int s1 = a + b + c - s0 - s2;

    if (t < DIMN * NPTS) mS[t] = matrix[t];
    __syncthreads();

    if (t < DIMN * RESTN) {
        int i = t / RESTN, m = t - i * RESTN;
        int rm = m + (m >= s0); rm += (rm >= s1); rm += (rm >= s2);
        int ci_ = (i == 0) ? a : ((i == 1) ? b : c);
        projS[i][m] = mS[ci_] * mS[rm]
                    + mS[NPTS + ci_] * mS[NPTS + rm]
                    + mS[2 * NPTS + ci_] * mS[2 * NPTS + rm];
    } else if (t < DIMN * RESTN + 9) {
        int q = t - DIMN * RESTN;
        int i = q / 3, j = q - 3 * i;
        int ci_ = (i == 0) ? a : ((i == 1) ? b : c);
        int cj_ = (j == 0) ? a : ((j == 1) ? b : c);
        gramS[q] = mS[ci_] * mS[cj_]
                 + mS[NPTS + ci_] * mS[NPTS + cj_]
                 + mS[2 * NPTS + ci_] * mS[2 * NPTS + cj_];
    }
    __syncthreads();

    if (t < 9) g_vecT[(size_t)t * PP + p] = gramS[t];

    if (t < KK) {
        const int k = t;
        const float w0 = WsIn[k * 3 + 0];
        const float w1 = WsIn[k * 3 + 1];
        const float w2 = WsIn[k * 3 + 2];

        float v[32];
#pragma unroll
        for (int m = 0; m < RESTN; ++m)
            v[m] = fmaf(projS[2][m], w2, fmaf(projS[1][m], w1, projS[0][m] * w0));
        const float INF = __int_as_float(0x7f800000);
#pragma unroll
        for (int m = RESTN; m < 32; ++m) v[m] = INF;

        // fully-unrolled 32-element bitonic sort (ascending), registers only
#pragma unroll
        for (int size = 2; size <= 32; size <<= 1) {
#pragma unroll
            for (int stride = size >> 1; stride > 0; stride >>= 1) {
#pragma unroll
                for (int i = 0; i < 32; ++i) {
                    int j = i ^ stride;
                    if (j > i) {
                        bool up = ((i & size) == 0);
                        float x = v[i], y = v[j];
                        float lo = fminf(x, y), hi = fmaxf(x, y);
                        v[i] = up ? lo : hi;
                        v[j] = up ? hi : lo;
                    }
                }
            }
        }

        float e = 0.0f;
#pragma unroll
        for (int m = 0; m < RESTN; ++m)
            e = fmaf(g_wdT[m * KK + k], v[m], e);   // coalesced, L1-resident
        g_vecT[(size_t)(9 + k) * PP + p] = e;
    }
}

// ------------------------- K2: sm2T[k][p] = vec[p] . Ws_out[k] -------------------------
// packed f32x2 FMA: pair along k; weight pairs come free from float4 smem loads
#define TP 64
#define JC 38
__device__ __forceinline__ void ffma2(unsigned long long& d,
                                      unsigned long long a,
                                      unsigned long long b) {
    asm("fma.rn.f32x2 %0, %1, %2, %0;" : "+l"(d) : "l"(a), "l"(b));
}
__device__ __forceinline__ unsigned long long dup_f32(float x) {
    unsigned long long r;
    unsigned int u = __float_as_uint(x);
    asm("mov.b64 %0, {%1, %1};" : "=l"(r) : "r"(u));
    return r;
}

__global__ void k2_gemm() {
    __shared__ __align__(16) float vS[JC][TP];    // [j][p]   9.7 KB
    __shared__ __align__(16) float wS[JC][192];   // [j][k]  29.2 KB

    const int p0 = blockIdx.x * TP;
    const int t  = threadIdx.x;         // 256
    const int pt = t & 15;              // 16 p-threads (4 p each)
    const int kt = t >> 4;              // 16 k-threads (12 k each = 6 pairs)

    unsigned long long acc2[4][6];      // [p][k-pair]
#pragma unroll
    for (int r0 = 0; r0 < 4; ++r0)
#pragma unroll
        for (int cc = 0; cc < 6; ++cc) acc2[r0][cc] = 0ull;

    for (int j0 = 0; j0 < DE; j0 += JC) {       // 5 iterations (190 = 5*38)
        __syncthreads();
        for (int idx = t; idx < JC * TP; idx += 256) {
            int row = idx >> 6;              // j within tile
            int col = idx & 63;              // p within tile
            int p = p0 + col;
            vS[row][col] = (p < PP) ? g_vecT[(size_t)(j0 + row) * PP + p] : 0.0f;
        }
        for (int idx = t; idx < JC * 192; idx += 256) {
            int row = idx / 192;
            int col = idx - row * 192;
            wS[row][col] = g_wsT[(j0 + row) * 192 + col];
        }
        __syncthreads();

#pragma unroll
        for (int jj = 0; jj < JC; ++jj) {
            float4 rv = *reinterpret_cast<const float4*>(&vS[jj][pt * 4]);
            unsigned long long rr2[4] = {dup_f32(rv.x), dup_f32(rv.y),
                                         dup_f32(rv.z), dup_f32(rv.w)};
            const unsigned long long* wrow =
                reinterpret_cast<const unsigned long long*>(&wS[jj][0]);
            unsigned long long w2[6];
#pragma unroll
            for (int cc = 0; cc < 6; ++cc) w2[cc] = wrow[kt * 6 + cc];
#pragma unroll
            for (int cc = 0; cc < 6; ++cc)
#pragma unroll
                for (int r0 = 0; r0 < 4; ++r0)
                    ffma2(acc2[r0][cc], rr2[r0], w2[cc]);
        }
    }

    const bool full = (p0 + TP <= PP);
    // unpack: acc2[r0][cc] holds k = kt*12 + 2*cc (lo lane) and +1 (hi lane)
#pragma unroll
    for (int cc = 0; cc < 6; ++cc) {
#pragma unroll
        for (int half = 0; half < 2; ++half) {
            int k = kt * 12 + 2 * cc + half;
            if (k >= KK) continue;
            float a0, a1, a2, a3;
            if (half == 0) {
                a0 = __uint_as_float((unsigned int)(acc2[0][cc] & 0xffffffffull));
                a1 = __uint_as_float((unsigned int)(acc2[1][cc] & 0xffffffffull));
                a2 = __uint_as_float((unsigned int)(acc2[2][cc] & 0xffffffffull));
                a3 = __uint_as_float((unsigned int)(acc2[3][cc] & 0xffffffffull));
            } else {
                a0 = __uint_as_float((unsigned int)(acc2[0][cc] >> 32));
                a1 = __uint_as_float((unsigned int)(acc2[1][cc] >> 32));
                a2 = __uint_as_float((unsigned int)(acc2[2][cc] >> 32));
                a3 = __uint_as_float((unsigned int)(acc2[3][cc] >> 32));
            }
            size_t base = (size_t)k * PP + p0 + pt * 4;
            if (full) {
                *reinterpret_cast<float4*>(&g_sm2T[base]) = make_float4(a0, a1, a2, a3);
            } else {
                float av[4] = {a0, a1, a2, a3};
#pragma unroll
                for (int r0 = 0; r0 < 4; ++r0) {
                    int p = p0 + pt * 4 + r0;
                    if (p < PP) g_sm2T[(size_t)k * PP + p] = av[r0];
                }
            }
        }
    }
}

// ------------------------- K3a: sort half-columns (512 thr x 24 items) -----------------
using K3aSorter = cub::BlockRadixSort<float, K3A_THREADS, K3A_IPT, cub::NullType, 5>;

__global__ void __launch_bounds__(K3A_THREADS)
k3a_sorthalf() {
    extern __shared__ __align__(16) char smem_raw[];
    typename K3aSorter::TempStorage& tmp =
        *reinterpret_cast<typename K3aSorter::TempStorage*>(smem_raw);

    const int k    = blockIdx.x >> 1;
    const int half = blockIdx.x & 1;
    const int t    = threadIdx.x;
    const float INF = __int_as_float(0x7f800000);

    const float* src = g_sm2T + (size_t)k * PP + half * HALF_N;
    const int start = t * K3A_IPT;

    float keys[K3A_IPT];
    if (start + K3A_IPT <= HALF_N) {
        const float4* s4 = reinterpret_cast<const float4*>(src + start);
#pragma unroll
        for (int q = 0; q < K3A_IPT / 4; ++q) {
            float4 v = s4[q];
            keys[q * 4 + 0] = v.x; keys[q * 4 + 1] = v.y;
            keys[q * 4 + 2] = v.z; keys[q * 4 + 3] = v.w;
        }
    } else {
#pragma unroll
        for (int q = 0; q < K3A_IPT; ++q)
            keys[q] = (start + q < HALF_N) ? src[start + q] : INF;
    }

    K3aSorter(tmp).Sort(keys);

    float4* dst = reinterpret_cast<float4*>(
        g_srt + (size_t)(k * 2 + half) * HALF_PAD + start);
#pragma unroll
    for (int q = 0; q < K3A_IPT / 4; ++q)
        dst[q] = make_float4(keys[q * 4 + 0], keys[q * 4 + 1],
                             keys[q * 4 + 2], keys[q * 4 + 3]);
}

// ------------------------- K3b: merge-path merge + weighted dot ------------------------
__global__ void __launch_bounds__(1024)
k3b_mergedot(const float* __restrict__ WdOut, float* __restrict__ out) {
    __shared__ float red[32];
    const int k = blockIdx.x;
    const int t = threadIdx.x;

    const float* A = g_srt + (size_t)(k * 2) * HALF_PAD;
    const float* B = A + HALF_PAD;
    const int nA = HALF_N, nB = HALF_N;

    const int d0 = t * 24;             // 1015*24 = 24360 exactly
    float acc = 0.0f;
    if (d0 < PP) {
        // merge-path partition: i = count taken from A in first d0 outputs
        // tie rule: A wins (A[i] <= B[j] -> take A)
        int lo = max(0, d0 - nB), hi = min(d0, nA);
        while (lo < hi) {
            int mid = (lo + hi) >> 1;
            if (A[mid] <= B[d0 - mid - 1]) lo = mid + 1;
            else hi = mid;
        }
        int i = lo, j = d0 - lo;

        const float* wd = WdOut + (size_t)k * PP + d0;
#pragma unroll 4
        for (int q = 0; q < 24; ++q) {
            bool takeA = (j >= nB) || (i < nA && A[i] <= B[j]);
            float val = takeA ? A[i] : B[j];
            i += takeA;
            j += !takeA;
            acc = fmaf(wd[q], val, acc);
        }
    }

#pragma unroll
    for (int o = 16; o > 0; o >>= 1)
        acc += __shfl_down_sync(0xffffffffu, acc, o);
    if ((t & 31) == 0) red[t >> 5] = acc;
    __syncthreads();
    if (t < 32) {
        float x = red[t];
#pragma unroll
        for (int o = 16; o > 0; o >>= 1)
            x += __shfl_down_sync(0xffffffffu, x, o);
        if (t == 0) out[k] = x;
    }
}

// ------------------------- launch -------------------------
extern "C" void kernel_launch(void* const* d_in, const int* in_sizes, int n_in,
                              void* d_out, int out_size) {
    const float* matrix = (const float*)d_in[0];
    const float* WsIn   = (const float*)d_in[1];
    const float* WdIn   = (const float*)d_in[2];
    const float* WsOut  = (const float*)d_in[3];
    const float* WdOut  = (const float*)d_in[4];
    float* out = (float*)d_out;

    const int k3a_smem = (int)sizeof(typename K3aSorter::TempStorage);
    cudaFuncSetAttribute(k3a_sorthalf, cudaFuncAttributeMaxDynamicSharedMemorySize,
                         k3a_smem);

    k0_transpose<<<DE, 192>>>(WsOut);
    k0b_transpose<<<RESTN, 192>>>(WdIn);
    k1_vec<<<PP, 192>>>(matrix, WsIn);
    k2_gemm<<<(PP + TP - 1) / TP, 256>>>();
    k3a_sorthalf<<<KK * 2, K3A_THREADS, k3a_smem>>>();
    k3b_mergedot<<<KK, 1024>>>(WdOut, out);
}